// round 2
// baseline (speedup 1.0000x reference)
#include <cuda_runtime.h>

// Low-rank RNN: B=256 independent sequences, S=512 steps, H=512, R=2, I=3, O=3.
// One CTA (256 threads) per batch element; each thread owns 2 adjacent h.
// Carried state per step is only p = h @ V^T (2 floats), reduced across the
// block each step. Output projection (O=3) folded into the same reduction.

#define BB 256
#define SS 512
#define II 3
#define HH 512
#define OO 3

__device__ __forceinline__ float tanh_fast(float x) {
    // tanh(x) = 1 - 2/(e^{2x}+1); safe at both infinities, ~1e-7 abs error.
    float e = __expf(2.0f * x);
    return 1.0f - __fdividef(2.0f, e + 1.0f);
}

__global__ __launch_bounds__(256, 2)
void lr_rnn_kernel(const float* __restrict__ x,   // [B,S,I]
                   const float* __restrict__ U,   // [R,H]
                   const float* __restrict__ V,   // [R,H]
                   const float* __restrict__ Wi,  // [H,I]
                   const float* __restrict__ bi,  // [H]
                   const float* __restrict__ Wo,  // [O,H]
                   const float* __restrict__ bo,  // [O]
                   float* __restrict__ out_y,     // [B,S,O]
                   float* __restrict__ out_h,     // [B,H]
                   float* __restrict__ out_r)     // [B,S,H]
{
    __shared__ float  sx[SS * II];        // this batch's x, 6 KB
    __shared__ float4 part4[2][8];        // per-warp partials: pv0,pv1,po0,po1
    __shared__ float  part1[2][8];        // per-warp partial: po2

    const int tid  = threadIdx.x;
    const int b    = blockIdx.x;
    const int wid  = tid >> 5;
    const int lane = tid & 31;
    const int t2   = tid * 2;             // first of this thread's two h indices

    // Stage x[b,:,:] into shared memory (coalesced).
    const float* xb = x + (size_t)b * (SS * II);
    for (int i = tid; i < SS * II; i += 256) sx[i] = xb[i];

    // Per-thread loop-invariant weights (2 h lanes each).
    const float2 u0 = *(const float2*)(U + t2);
    const float2 u1 = *(const float2*)(U + HH + t2);
    const float2 v0 = *(const float2*)(V + t2);
    const float2 v1 = *(const float2*)(V + HH + t2);
    const float2 w0 = *(const float2*)(Wo + t2);
    const float2 w1 = *(const float2*)(Wo + HH + t2);
    const float2 w2 = *(const float2*)(Wo + 2 * HH + t2);
    const float2 b2 = *(const float2*)(bi + t2);
    const float wiA0 = Wi[3 * t2 + 0], wiA1 = Wi[3 * t2 + 1], wiA2 = Wi[3 * t2 + 2];
    const float wiB0 = Wi[3 * t2 + 3], wiB1 = Wi[3 * t2 + 4], wiB2 = Wi[3 * t2 + 5];
    const float bo_t = (tid < OO) ? bo[tid] : 0.0f;

    float* rb = out_r + (size_t)b * (SS * HH);
    float* yb = out_y + (size_t)b * (SS * OO);

    __syncthreads();

    // Input projection for step 0 (h0 = 0 so p starts at 0).
    float p0 = 0.0f, p1 = 0.0f;
    float xa = sx[0], xbv = sx[1], xc = sx[2];
    float base0 = fmaf(xc, wiA2, fmaf(xbv, wiA1, fmaf(xa, wiA0, b2.x)));
    float base1 = fmaf(xc, wiB2, fmaf(xbv, wiB1, fmaf(xa, wiB0, b2.y)));

    float a0 = 0.0f, a1 = 0.0f;

    for (int s = 0; s < SS; ++s) {
        // c = base + p @ U   (the only p-dependent work)
        float c0 = fmaf(p1, u1.x, fmaf(p0, u0.x, base0));
        float c1 = fmaf(p1, u1.y, fmaf(p0, u0.y, base1));
        a0 = tanh_fast(c0);
        a1 = tanh_fast(c1);

        // r_out row (fire-and-forget, coalesced 8B/thread)
        *(float2*)(rb + s * HH + t2) = make_float2(a0, a1);

        // Per-thread partials: p_new = a@V^T, o = a@Wo^T
        float pv0 = fmaf(a1, v0.y, a0 * v0.x);
        float pv1 = fmaf(a1, v1.y, a0 * v1.x);
        float po0 = fmaf(a1, w0.y, a0 * w0.x);
        float po1 = fmaf(a1, w1.y, a0 * w1.x);
        float po2 = fmaf(a1, w2.y, a0 * w2.x);

        // Warp reduction (5 interleaved butterfly chains).
        #pragma unroll
        for (int off = 16; off; off >>= 1) {
            pv0 += __shfl_xor_sync(0xffffffffu, pv0, off);
            pv1 += __shfl_xor_sync(0xffffffffu, pv1, off);
            po0 += __shfl_xor_sync(0xffffffffu, po0, off);
            po1 += __shfl_xor_sync(0xffffffffu, po1, off);
            po2 += __shfl_xor_sync(0xffffffffu, po2, off);
        }

        const int bsel = s & 1;  // double buffer -> single bar per step
        if (lane == 0) {
            part4[bsel][wid] = make_float4(pv0, pv1, po0, po1);
            part1[bsel][wid] = po2;
        }

        // Precompute next step's input projection in the reduce shadow.
        if (s + 1 < SS) {
            float y0 = sx[(s + 1) * 3 + 0];
            float y1 = sx[(s + 1) * 3 + 1];
            float y2 = sx[(s + 1) * 3 + 2];
            base0 = fmaf(y2, wiA2, fmaf(y1, wiA1, fmaf(y0, wiA0, b2.x)));
            base1 = fmaf(y2, wiB2, fmaf(y1, wiB1, fmaf(y0, wiB0, b2.y)));
        }

        __syncthreads();

        // Every thread sums the 8 warp partials itself (no second barrier).
        float q0 = 0.0f, q1 = 0.0f;
        #pragma unroll
        for (int w = 0; w < 8; ++w) {
            float4 pw = part4[bsel][w];
            q0 += pw.x;
            q1 += pw.y;
        }
        p0 = q0;
        p1 = q1;

        if (tid < OO) {
            float o = bo_t;
            #pragma unroll
            for (int w = 0; w < 8; ++w) {
                float4 pw = part4[bsel][w];
                o += (tid == 0) ? pw.z : (tid == 1) ? pw.w : part1[bsel][w];
            }
            yb[s * OO + tid] = o;
        }
    }

    // h_last = h at s = S-1
    *(float2*)(out_h + (size_t)b * HH + t2) = make_float2(a0, a1);
}

extern "C" void kernel_launch(void* const* d_in, const int* in_sizes, int n_in,
                              void* d_out, int out_size) {
    const float* x  = (const float*)d_in[0];
    const float* U  = (const float*)d_in[1];
    const float* V  = (const float*)d_in[2];
    const float* Wi = (const float*)d_in[3];
    const float* bi = (const float*)d_in[4];
    const float* Wo = (const float*)d_in[5];
    const float* bo = (const float*)d_in[6];

    float* out   = (float*)d_out;
    float* out_y = out;                                  // [B,S,O] = 393216
    float* out_h = out + (size_t)BB * SS * OO;           // [B,H]   = 131072
    float* out_r = out_h + (size_t)BB * HH;              // [B,S,H]

    lr_rnn_kernel<<<BB, 256>>>(x, U, V, Wi, bi, Wo, bo, out_y, out_h, out_r);
}

// round 14
// speedup vs baseline: 2.5701x; 2.5701x over previous
#include <cuda_runtime.h>

// Low-rank RNN: B=256 independent sequences, S=512 steps, H=512, R=2, I=3, O=3.
// One CTA (128 threads) per batch element; each thread owns 4 adjacent h.
// Carried state per step is p = h @ V^T (2 floats) reduced across the block.
// Output projection (O=3) folded into the same per-step reduction.

#define BB 256
#define SS 512
#define II 3
#define HH 512
#define OO 3

__device__ __forceinline__ float tanh_mufu(float x) {
    float y;
    asm("tanh.approx.f32 %0, %1;" : "=f"(y) : "f"(x));
    return y;
}

__global__ __launch_bounds__(128, 2)
void lr_rnn_kernel(const float* __restrict__ x,   // [B,S,I]
                   const float* __restrict__ U,   // [R,H]
                   const float* __restrict__ V,   // [R,H]
                   const float* __restrict__ Wi,  // [H,I]
                   const float* __restrict__ bi,  // [H]
                   const float* __restrict__ Wo,  // [O,H]
                   const float* __restrict__ bo,  // [O]
                   float* __restrict__ out_y,     // [B,S,O]
                   float* __restrict__ out_h,     // [B,H]
                   float* __restrict__ out_r)     // [B,S,H]
{
    __shared__ float sx[SS * II];                     // 6 KB of x for this batch
    __shared__ __align__(16) float2 pvbuf[2][4];      // per-warp (pv0,pv1)
    __shared__ __align__(16) float4 pobuf[2][4];      // per-warp (po0,po1,po2,_)

    const int tid  = threadIdx.x;
    const int b    = blockIdx.x;
    const int wid  = tid >> 5;
    const int lane = tid & 31;
    const int t4   = tid * 4;            // first of this thread's four h indices

    // Stage x[b,:,:] into shared (coalesced float4).
    {
        const float4* xb4 = (const float4*)(x + (size_t)b * (SS * II));
        float4* sx4 = (float4*)sx;
        #pragma unroll
        for (int i = 0; i < 3; ++i) sx4[tid + 128 * i] = xb4[tid + 128 * i];
    }

    // Loop-invariant weights for this thread's 4 h lanes.
    const float4 u0 = *(const float4*)(U + t4);
    const float4 u1 = *(const float4*)(U + HH + t4);
    const float4 v0 = *(const float4*)(V + t4);
    const float4 v1 = *(const float4*)(V + HH + t4);
    const float4 w0 = *(const float4*)(Wo + t4);
    const float4 w1 = *(const float4*)(Wo + HH + t4);
    const float4 w2 = *(const float4*)(Wo + 2 * HH + t4);
    const float4 bi4 = *(const float4*)(bi + t4);
    float wi[12];  // Wi rows 4t..4t+3 (3 floats each)
    {
        const float4* wp = (const float4*)(Wi + 3 * t4);
        float4 q0 = wp[0], q1 = wp[1], q2 = wp[2];
        wi[0]=q0.x; wi[1]=q0.y; wi[2]=q0.z; wi[3]=q0.w;
        wi[4]=q1.x; wi[5]=q1.y; wi[6]=q1.z; wi[7]=q1.w;
        wi[8]=q2.x; wi[9]=q2.y; wi[10]=q2.z; wi[11]=q2.w;
    }
    const float bo_t = (tid < OO) ? bo[tid] : 0.0f;

    float* rb = out_r + (size_t)b * (SS * HH);
    float* yb = out_y + (size_t)b * (SS * OO);

    __syncthreads();

    // base for step 0 (h0 = 0 so p starts at 0)
    float p0 = 0.0f, p1 = 0.0f;
    float base[4];
    {
        float y0 = sx[0], y1 = sx[1], y2 = sx[2];
        #pragma unroll
        for (int i = 0; i < 4; ++i)
            base[i] = fmaf(y2, wi[3*i+2], fmaf(y1, wi[3*i+1],
                      fmaf(y0, wi[3*i+0], ((const float*)&bi4)[i])));
    }

    float a0 = 0.f, a1 = 0.f, a2 = 0.f, a3 = 0.f;

    #pragma unroll 2
    for (int s = 0; s < SS; ++s) {
        const int bsel = s & 1;

        // c = base + p @ U ; a = tanh(c)
        a0 = tanh_mufu(fmaf(p1, u1.x, fmaf(p0, u0.x, base[0])));
        a1 = tanh_mufu(fmaf(p1, u1.y, fmaf(p0, u0.y, base[1])));
        a2 = tanh_mufu(fmaf(p1, u1.z, fmaf(p0, u0.z, base[2])));
        a3 = tanh_mufu(fmaf(p1, u1.w, fmaf(p0, u0.w, base[3])));

        // r_out row: one STG.128 per thread, coalesced
        *(float4*)(rb + s * HH + t4) = make_float4(a0, a1, a2, a3);

        // p partials first (they gate the recurrence)
        float pv0 = fmaf(a3, v0.w, fmaf(a2, v0.z, fmaf(a1, v0.y, a0 * v0.x)));
        float pv1 = fmaf(a3, v1.w, fmaf(a2, v1.z, fmaf(a1, v1.y, a0 * v1.x)));
        #pragma unroll
        for (int off = 16; off; off >>= 1) {
            pv0 += __shfl_xor_sync(0xffffffffu, pv0, off);
            pv1 += __shfl_xor_sync(0xffffffffu, pv1, off);
        }
        if (lane == 0) pvbuf[bsel][wid] = make_float2(pv0, pv1);

        // output-projection partials (off the recurrence path)
        float po0 = fmaf(a3, w0.w, fmaf(a2, w0.z, fmaf(a1, w0.y, a0 * w0.x)));
        float po1 = fmaf(a3, w1.w, fmaf(a2, w1.z, fmaf(a1, w1.y, a0 * w1.x)));
        float po2 = fmaf(a3, w2.w, fmaf(a2, w2.z, fmaf(a1, w2.y, a0 * w2.x)));
        #pragma unroll
        for (int off = 16; off; off >>= 1) {
            po0 += __shfl_xor_sync(0xffffffffu, po0, off);
            po1 += __shfl_xor_sync(0xffffffffu, po1, off);
            po2 += __shfl_xor_sync(0xffffffffu, po2, off);
        }
        if (lane == 0) pobuf[bsel][wid] = make_float4(po0, po1, po2, 0.0f);

        // next step's input projection in the barrier shadow
        if (s + 1 < SS) {
            float y0 = sx[(s + 1) * 3 + 0];
            float y1 = sx[(s + 1) * 3 + 1];
            float y2 = sx[(s + 1) * 3 + 2];
            #pragma unroll
            for (int i = 0; i < 4; ++i)
                base[i] = fmaf(y2, wi[3*i+2], fmaf(y1, wi[3*i+1],
                          fmaf(y0, wi[3*i+0], ((const float*)&bi4)[i])));
        }

        __syncthreads();

        // every thread sums the 4 warp partials (2 LDS.128 + 6 FADD)
        {
            const float4* pv4 = (const float4*)&pvbuf[bsel][0];
            float4 A = pv4[0], Bv = pv4[1];
            p0 = (A.x + A.z) + (Bv.x + Bv.z);
            p1 = (A.y + A.w) + (Bv.y + Bv.w);
        }

        if (tid < OO) {
            float o = bo_t;
            #pragma unroll
            for (int w = 0; w < 4; ++w)
                o += ((const float*)&pobuf[bsel][w])[tid];
            yb[s * OO + tid] = o;
        }
    }

    // h_last = h at s = S-1
    *(float4*)(out_h + (size_t)b * HH + t4) = make_float4(a0, a1, a2, a3);
}

extern "C" void kernel_launch(void* const* d_in, const int* in_sizes, int n_in,
                              void* d_out, int out_size) {
    const float* x  = (const float*)d_in[0];
    const float* U  = (const float*)d_in[1];
    const float* V  = (const float*)d_in[2];
    const float* Wi = (const float*)d_in[3];
    const float* bi = (const float*)d_in[4];
    const float* Wo = (const float*)d_in[5];
    const float* bo = (const float*)d_in[6];

    float* out   = (float*)d_out;
    float* out_y = out;                                  // [B,S,O]
    float* out_h = out + (size_t)BB * SS * OO;           // [B,H]
    float* out_r = out_h + (size_t)BB * HH;              // [B,S,H]

    lr_rnn_kernel<<<BB, 128>>>(x, U, V, Wi, bi, Wo, bo, out_y, out_h, out_r);
}